// round 15
// baseline (speedup 1.0000x reference)
#include <cuda_runtime.h>
#include <cuda_fp16.h>

#define POOL 7
#define CELLS (POOL * POOL)

// fp16 copies of feat4/feat5 (B=2, C=256): 4MB + 1MB device scratch
__device__ __half g_f4h[2 * 64 * 64 * 256];
__device__ __half g_f5h[2 * 32 * 32 * 256];

#define CVT4_BLOCKS 1024   // 2*64*64*256/8 threads / 256
#define CVT5_BLOCKS 256    // 2*32*32*256/8 threads / 256
#define CVT_BLOCKS  (CVT4_BLOCKS + CVT5_BLOCKS)

__device__ __forceinline__ float4 lerp4(float4 tl, float4 tr, float4 bl, float4 br,
                                        float fx, float fy)
{
    float4 r;
    float tx = tl.x + (tr.x - tl.x) * fx;
    float ty = tl.y + (tr.y - tl.y) * fx;
    float tz = tl.z + (tr.z - tl.z) * fx;
    float tw = tl.w + (tr.w - tl.w) * fx;
    float bx = bl.x + (br.x - bl.x) * fx;
    float by = bl.y + (br.y - bl.y) * fx;
    float bz = bl.z + (br.z - bl.z) * fx;
    float bw = bl.w + (br.w - bl.w) * fx;
    r.x = tx + (bx - tx) * fy;
    r.y = ty + (by - ty) * fy;
    r.z = tz + (bz - tz) * fy;
    r.w = tw + (bw - tw) * fy;
    return r;
}

__device__ __forceinline__ float4 lerp4h(uint2 TL, uint2 TR, uint2 BL, uint2 BR,
                                         float fx, float fy)
{
    float2 tl0 = __half22float2(*reinterpret_cast<__half2*>(&TL.x));
    float2 tl1 = __half22float2(*reinterpret_cast<__half2*>(&TL.y));
    float2 tr0 = __half22float2(*reinterpret_cast<__half2*>(&TR.x));
    float2 tr1 = __half22float2(*reinterpret_cast<__half2*>(&TR.y));
    float2 bl0 = __half22float2(*reinterpret_cast<__half2*>(&BL.x));
    float2 bl1 = __half22float2(*reinterpret_cast<__half2*>(&BL.y));
    float2 br0 = __half22float2(*reinterpret_cast<__half2*>(&BR.x));
    float2 br1 = __half22float2(*reinterpret_cast<__half2*>(&BR.y));
    float4 tl = make_float4(tl0.x, tl0.y, tl1.x, tl1.y);
    float4 tr = make_float4(tr0.x, tr0.y, tr1.x, tr1.y);
    float4 bl = make_float4(bl0.x, bl0.y, bl1.x, bl1.y);
    float4 br = make_float4(br0.x, br0.y, br1.x, br1.y);
    return lerp4(tl, tr, bl, br, fx, fy);
}

// level selection — identical op order to reference
__device__ __forceinline__ int box_level(const float* __restrict__ bx, float scale,
                                         float& y1, float& x1, float& h, float& w)
{
    y1 = bx[0]; x1 = bx[1];
    float y2 = bx[2], x2 = bx[3];
    h = y2 - y1; w = x2 - x1;
    float lvl = log2f(sqrtf(h * w) / scale);
    float rl  = 4.0f + rintf(lvl);                 // half-to-even
    rl = fminf(fmaxf(rl, 2.0f), 5.0f);
    return (int)rl - 2;                            // 0..3
}

// ---- Kernel 1: level-2/3 boxes (fp32 direct) + fp16 conversion blocks ----
// bid < NB            -> box CTA (returns immediately unless li in {0,1})
// bid in [NB, NB+CVT) -> conversion CTA (f4 then f5 slices)
__global__ __launch_bounds__(256) void k1_direct23_cvt_kernel(
    const float* __restrict__ boxes,
    const float* __restrict__ meta,
    const float* __restrict__ f2,
    const float* __restrict__ f3,
    const float* __restrict__ f4,
    const float* __restrict__ f5,
    float* __restrict__ out,
    int N, int NB)
{
    const int tid = threadIdx.x;

    if (blockIdx.x >= NB) {
        // ---- conversion CTA: 8 elems per thread ----
        int cvtblk = blockIdx.x - NB;
        const float4* src;
        uint4* dst;
        int i;
        if (cvtblk < CVT4_BLOCKS) {
            i = cvtblk * 256 + tid;
            src = (const float4*)f4;
            dst = (uint4*)g_f4h;
        } else {
            i = (cvtblk - CVT4_BLOCKS) * 256 + tid;
            src = (const float4*)f5;
            dst = (uint4*)g_f5h;
        }
        float4 a = __ldg(src + 2 * i);
        float4 b = __ldg(src + 2 * i + 1);
        __half2 h0 = __floats2half2_rn(a.x, a.y);
        __half2 h1 = __floats2half2_rn(a.z, a.w);
        __half2 h2 = __floats2half2_rn(b.x, b.y);
        __half2 h3 = __floats2half2_rn(b.z, b.w);
        uint4 o;
        o.x = *reinterpret_cast<unsigned*>(&h0);
        o.y = *reinterpret_cast<unsigned*>(&h1);
        o.z = *reinterpret_cast<unsigned*>(&h2);
        o.w = *reinterpret_cast<unsigned*>(&h3);
        dst[i] = o;
        return;
    }

    // ---- box CTA ----
    const int bn = blockIdx.x;
    const float scale = 224.0f / sqrtf(meta[4] * meta[5]);
    float y1, x1, h, w;
    int li = box_level(boxes + (size_t)bn * 4, scale, y1, x1, h, w);
    if (li >= 2) return;                 // block-uniform: safe before syncs

    __shared__ int4   s_off[CELLS];
    __shared__ float2 s_f[CELLS];
    __shared__ const float4* s_base;

    if (tid < CELLS) {
        const int b = bn / N;
        int H  = 256 >> li;
        const float* fm = (li == 0) ? f2 : f3;
        int py = tid / POOL;
        int px = tid - py * POOL;
        float Hm1 = (float)(H - 1);
        float ys = y1 * Hm1 + (float)py * ((h * Hm1) / 6.0f);
        float xs = x1 * Hm1 + (float)px * ((w * Hm1) / 6.0f);
        float y0f = floorf(ys), x0f = floorf(xs);
        int y0  = min(max((int)y0f, 0), H - 1);
        int x0  = min(max((int)x0f, 0), H - 1);
        int y1i = min(y0 + 1, H - 1);
        int x1i = min(x0 + 1, H - 1);
        int4 off;
        off.x = (y0  * H + x0 ) * 64;
        off.y = (y0  * H + x1i) * 64;
        off.z = (y1i * H + x0 ) * 64;
        off.w = (y1i * H + x1i) * 64;
        s_off[tid] = off;
        s_f[tid] = make_float2(xs - x0f, ys - y0f);
        if (tid == 0) s_base = (const float4*)fm + (size_t)b * H * H * 64;
    }
    __syncthreads();

    const float4* base = s_base;
    const int c4  = tid & 63;
    const int grp = tid >> 6;
    float4* ob = (float4*)out + (size_t)bn * CELLS * 64 + c4;

    #pragma unroll 1
    for (int cell = grp; cell < CELLS; cell += 4) {
        int4   off = s_off[cell];
        float2 f   = s_f[cell];
        float4 tl = __ldg(base + off.x + c4);
        float4 tr = __ldg(base + off.y + c4);
        float4 bl = __ldg(base + off.z + c4);
        float4 br = __ldg(base + off.w + c4);
        __stcs(ob + cell * 64, lerp4(tl, tr, bl, br, f.x, f.y));
    }
}

// ---- Kernel 2: level-4/5 boxes from fp16 scratch ----
__global__ __launch_bounds__(256) void k2_half45_kernel(
    const float* __restrict__ boxes,
    const float* __restrict__ meta,
    float* __restrict__ out,
    int N)
{
    const int bn  = blockIdx.x;
    const int tid = threadIdx.x;

    const float scale = 224.0f / sqrtf(meta[4] * meta[5]);
    float y1, x1, h, w;
    int li = box_level(boxes + (size_t)bn * 4, scale, y1, x1, h, w);
    if (li < 2) return;                  // handled by kernel 1

    __shared__ int4   s_off[CELLS];
    __shared__ float2 s_f[CELLS];
    __shared__ const uint2* s_base;

    if (tid < CELLS) {
        const int b = bn / N;
        int H  = 256 >> li;              // 64 or 32
        const __half* hb = (li == 2) ? g_f4h : g_f5h;
        int py = tid / POOL;
        int px = tid - py * POOL;
        float Hm1 = (float)(H - 1);
        float ys = y1 * Hm1 + (float)py * ((h * Hm1) / 6.0f);
        float xs = x1 * Hm1 + (float)px * ((w * Hm1) / 6.0f);
        float y0f = floorf(ys), x0f = floorf(xs);
        int y0  = min(max((int)y0f, 0), H - 1);
        int x0  = min(max((int)x0f, 0), H - 1);
        int y1i = min(y0 + 1, H - 1);
        int x1i = min(x0 + 1, H - 1);
        int4 off;
        off.x = (y0  * H + x0 ) * 64;
        off.y = (y0  * H + x1i) * 64;
        off.z = (y1i * H + x0 ) * 64;
        off.w = (y1i * H + x1i) * 64;
        s_off[tid] = off;
        s_f[tid] = make_float2(xs - x0f, ys - y0f);
        if (tid == 0) s_base = (const uint2*)hb + (size_t)b * H * H * 64;
    }
    __syncthreads();

    const uint2* base = s_base;
    const int c4  = tid & 63;
    const int grp = tid >> 6;
    float4* ob = (float4*)out + (size_t)bn * CELLS * 64 + c4;

    #pragma unroll 1
    for (int cell = grp; cell < CELLS; cell += 4) {
        int4   off = s_off[cell];
        float2 f   = s_f[cell];
        uint2 tl = __ldg(base + off.x + c4);
        uint2 tr = __ldg(base + off.y + c4);
        uint2 bl = __ldg(base + off.z + c4);
        uint2 br = __ldg(base + off.w + c4);
        __stcs(ob + cell * 64, lerp4h(tl, tr, bl, br, f.x, f.y));
    }
}

// ---- generic fallback (any C divisible by 4, full fp32) ----

struct __align__(16) CellParam {
    const float4* tl; const float4* tr;
    const float4* bl; const float4* br;
    float fx, fy, pad0, pad1;
};

__global__ __launch_bounds__(256) void roialign_generic_kernel(
    const float* __restrict__ boxes, const float* __restrict__ meta,
    const float* __restrict__ f2, const float* __restrict__ f3,
    const float* __restrict__ f4, const float* __restrict__ f5,
    float* __restrict__ out, int N, int C)
{
    __shared__ CellParam cp[CELLS];
    const int bn  = blockIdx.x;
    const int tid = threadIdx.x;

    if (tid < CELLS) {
        const int b = bn / N;
        const float scale = 224.0f / sqrtf(meta[4] * meta[5]);
        float y1, x1, h, w;
        int li = box_level(boxes + (size_t)bn * 4, scale, y1, x1, h, w);
        int H  = 256 >> li;
        const float* fm = (li == 0) ? f2 : (li == 1) ? f3 : (li == 2) ? f4 : f5;
        const float* base = fm + (size_t)b * H * H * C;
        int py = tid / POOL;
        int px = tid - py * POOL;
        float Hm1 = (float)(H - 1);
        float ys = y1 * Hm1 + (float)py * ((h * Hm1) / 6.0f);
        float xs = x1 * Hm1 + (float)px * ((w * Hm1) / 6.0f);
        float y0f = floorf(ys), x0f = floorf(xs);
        int y0  = min(max((int)y0f, 0), H - 1);
        int x0  = min(max((int)x0f, 0), H - 1);
        int y1i = min(y0 + 1, H - 1);
        int x1i = min(x0 + 1, H - 1);
        CellParam p;
        p.tl = (const float4*)(base + (size_t)(y0  * H + x0 ) * C);
        p.tr = (const float4*)(base + (size_t)(y0  * H + x1i) * C);
        p.bl = (const float4*)(base + (size_t)(y1i * H + x0 ) * C);
        p.br = (const float4*)(base + (size_t)(y1i * H + x1i) * C);
        p.fx = xs - x0f;  p.fy = ys - y0f;
        p.pad0 = 0.f; p.pad1 = 0.f;
        cp[tid] = p;
    }
    __syncthreads();

    const int c4pc = C >> 2;
    const int c4   = tid % c4pc;
    const int cw   = tid / c4pc;
    const int cstr = blockDim.x / c4pc;
    float4* ob = (float4*)out + (size_t)bn * CELLS * c4pc;

    for (int cell = cw; cell < CELLS; cell += cstr) {
        float fx = cp[cell].fx, fy = cp[cell].fy;
        float4 tl = __ldg(cp[cell].tl + c4);
        float4 tr = __ldg(cp[cell].tr + c4);
        float4 bl = __ldg(cp[cell].bl + c4);
        float4 br = __ldg(cp[cell].br + c4);
        ob[cell * c4pc + c4] = lerp4(tl, tr, bl, br, fx, fy);
    }
}

extern "C" void kernel_launch(void* const* d_in, const int* in_sizes, int n_in,
                              void* d_out, int out_size) {
    const float* boxes = (const float*)d_in[0];
    const float* meta  = (const float*)d_in[1];
    const float* f2    = (const float*)d_in[2];
    const float* f3    = (const float*)d_in[3];
    const float* f4    = (const float*)d_in[4];
    const float* f5    = (const float*)d_in[5];
    float* out = (float*)d_out;

    int B  = in_sizes[1] / 14;
    int N  = in_sizes[0] / (4 * B);
    int C  = in_sizes[2] / (B * 256 * 256);
    int NB = B * N;

    if (C == 256 && B == 2) {
        k1_direct23_cvt_kernel<<<NB + CVT_BLOCKS, 256>>>(boxes, meta, f2, f3, f4, f5,
                                                         out, N, NB);
        k2_half45_kernel<<<NB, 256>>>(boxes, meta, out, N);
    } else {
        roialign_generic_kernel<<<NB, 256>>>(boxes, meta, f2, f3, f4, f5, out, N, C);
    }
}

// round 16
// speedup vs baseline: 1.1150x; 1.1150x over previous
#include <cuda_runtime.h>
#include <cuda_fp16.h>

#define POOL 7
#define CELLS (POOL * POOL)

// fp16 copies of feat4/feat5 (B=2, C=256): 4MB + 1MB device scratch
__device__ __half g_f4h[2 * 64 * 64 * 256];
__device__ __half g_f5h[2 * 32 * 32 * 256];

#define N8_F4 (2 * 64 * 64 * 256 / 8)   // 262144 uint4 outputs
#define N8_F5 (2 * 32 * 32 * 256 / 8)   //  65536
#define CVT_BLOCKS ((N8_F4 + N8_F5) / 256)   // 1280

// ---- merged conversion kernel: fp32 -> fp16 for f4 AND f5, one launch ----
__global__ __launch_bounds__(256) void cvt_all_kernel(
    const float4* __restrict__ f4, const float4* __restrict__ f5)
{
    int i = blockIdx.x * 256 + threadIdx.x;
    const float4* src;
    uint4* dst;
    if (i < N8_F4) {
        src = f4;
        dst = (uint4*)g_f4h;
    } else {
        i -= N8_F4;
        src = f5;
        dst = (uint4*)g_f5h;
    }
    float4 a = __ldg(src + 2 * i);
    float4 b = __ldg(src + 2 * i + 1);
    __half2 h0 = __floats2half2_rn(a.x, a.y);
    __half2 h1 = __floats2half2_rn(a.z, a.w);
    __half2 h2 = __floats2half2_rn(b.x, b.y);
    __half2 h3 = __floats2half2_rn(b.z, b.w);
    uint4 o;
    o.x = *reinterpret_cast<unsigned*>(&h0);
    o.y = *reinterpret_cast<unsigned*>(&h1);
    o.z = *reinterpret_cast<unsigned*>(&h2);
    o.w = *reinterpret_cast<unsigned*>(&h3);
    dst[i] = o;
}

__device__ __forceinline__ float4 lerp4(float4 tl, float4 tr, float4 bl, float4 br,
                                        float fx, float fy)
{
    float4 r;
    float tx = tl.x + (tr.x - tl.x) * fx;
    float ty = tl.y + (tr.y - tl.y) * fx;
    float tz = tl.z + (tr.z - tl.z) * fx;
    float tw = tl.w + (tr.w - tl.w) * fx;
    float bx = bl.x + (br.x - bl.x) * fx;
    float by = bl.y + (br.y - bl.y) * fx;
    float bz = bl.z + (br.z - bl.z) * fx;
    float bw = bl.w + (br.w - bl.w) * fx;
    r.x = tx + (bx - tx) * fy;
    r.y = ty + (by - ty) * fy;
    r.z = tz + (bz - tz) * fy;
    r.w = tw + (bw - tw) * fy;
    return r;
}

__device__ __forceinline__ float4 lerp4h(uint2 TL, uint2 TR, uint2 BL, uint2 BR,
                                         float fx, float fy)
{
    float2 tl0 = __half22float2(*reinterpret_cast<__half2*>(&TL.x));
    float2 tl1 = __half22float2(*reinterpret_cast<__half2*>(&TL.y));
    float2 tr0 = __half22float2(*reinterpret_cast<__half2*>(&TR.x));
    float2 tr1 = __half22float2(*reinterpret_cast<__half2*>(&TR.y));
    float2 bl0 = __half22float2(*reinterpret_cast<__half2*>(&BL.x));
    float2 bl1 = __half22float2(*reinterpret_cast<__half2*>(&BL.y));
    float2 br0 = __half22float2(*reinterpret_cast<__half2*>(&BR.x));
    float2 br1 = __half22float2(*reinterpret_cast<__half2*>(&BR.y));
    float4 tl = make_float4(tl0.x, tl0.y, tl1.x, tl1.y);
    float4 tr = make_float4(tr0.x, tr0.y, tr1.x, tr1.y);
    float4 bl = make_float4(bl0.x, bl0.y, bl1.x, bl1.y);
    float4 br = make_float4(br0.x, br0.y, br1.x, br1.y);
    return lerp4(tl, tr, bl, br, fx, fy);
}

// ---- main kernel (C == 256): one box per 256-thread CTA ----
// Levels 2/3 read fp32 inputs directly; levels 4/5 read fp16 scratch.
__global__ __launch_bounds__(256) void roialign_c256_kernel(
    const float* __restrict__ boxes,
    const float* __restrict__ meta,
    const float* __restrict__ f2,
    const float* __restrict__ f3,
    float* __restrict__ out,
    int N)
{
    __shared__ int4   s_off[CELLS];
    __shared__ float2 s_f[CELLS];
    __shared__ const float4* s_basef;
    __shared__ const uint2*  s_baseh;
    __shared__ int s_half;

    const int bn  = blockIdx.x;
    const int tid = threadIdx.x;

    if (tid < CELLS) {
        const int b = bn / N;
        const float* bx = boxes + (size_t)bn * 4;
        float y1 = bx[0], x1 = bx[1], y2 = bx[2], x2 = bx[3];
        float h = y2 - y1, w = x2 - x1;

        float scale = 224.0f / sqrtf(meta[4] * meta[5]);
        float lvl = log2f(sqrtf(h * w) / scale);
        float rl  = 4.0f + rintf(lvl);                 // half-to-even
        rl = fminf(fmaxf(rl, 2.0f), 5.0f);
        int li = (int)rl - 2;
        int H  = 256 >> li;

        int py = tid / POOL;
        int px = tid - py * POOL;

        float Hm1 = (float)(H - 1);
        float ys = y1 * Hm1 + (float)py * ((h * Hm1) / 6.0f);
        float xs = x1 * Hm1 + (float)px * ((w * Hm1) / 6.0f);

        float y0f = floorf(ys), x0f = floorf(xs);
        int y0  = min(max((int)y0f, 0), H - 1);
        int x0  = min(max((int)x0f, 0), H - 1);
        int y1i = min(y0 + 1, H - 1);
        int x1i = min(x0 + 1, H - 1);

        int4 off;
        off.x = (y0  * H + x0 ) * 64;
        off.y = (y0  * H + x1i) * 64;
        off.z = (y1i * H + x0 ) * 64;
        off.w = (y1i * H + x1i) * 64;
        s_off[tid] = off;
        s_f[tid] = make_float2(xs - x0f, ys - y0f);

        if (tid == 0) {
            if (li >= 2) {
                s_half = 1;
                const __half* hb = (li == 2) ? g_f4h : g_f5h;
                s_baseh = (const uint2*)hb + (size_t)b * H * H * 64;
            } else {
                s_half = 0;
                const float* fm = (li == 0) ? f2 : f3;
                s_basef = (const float4*)fm + (size_t)b * H * H * 64;
            }
        }
    }
    __syncthreads();

    const int c4  = tid & 63;
    const int grp = tid >> 6;
    float4* ob = (float4*)out + (size_t)bn * CELLS * 64 + c4;

    if (s_half) {
        const uint2* base = s_baseh;
        #pragma unroll 1
        for (int cell = grp; cell < CELLS; cell += 4) {
            int4   off = s_off[cell];
            float2 f   = s_f[cell];
            uint2 tl = __ldg(base + off.x + c4);
            uint2 tr = __ldg(base + off.y + c4);
            uint2 bl = __ldg(base + off.z + c4);
            uint2 br = __ldg(base + off.w + c4);
            __stcs(ob + cell * 64, lerp4h(tl, tr, bl, br, f.x, f.y));
        }
    } else {
        const float4* base = s_basef;
        #pragma unroll 1
        for (int cell = grp; cell < CELLS; cell += 4) {
            int4   off = s_off[cell];
            float2 f   = s_f[cell];
            float4 tl = __ldg(base + off.x + c4);
            float4 tr = __ldg(base + off.y + c4);
            float4 bl = __ldg(base + off.z + c4);
            float4 br = __ldg(base + off.w + c4);
            __stcs(ob + cell * 64, lerp4(tl, tr, bl, br, f.x, f.y));
        }
    }
}

// ---- generic fallback (any C divisible by 4, full fp32) ----

struct __align__(16) CellParam {
    const float4* tl; const float4* tr;
    const float4* bl; const float4* br;
    float fx, fy, pad0, pad1;
};

__global__ __launch_bounds__(256) void roialign_generic_kernel(
    const float* __restrict__ boxes, const float* __restrict__ meta,
    const float* __restrict__ f2, const float* __restrict__ f3,
    const float* __restrict__ f4, const float* __restrict__ f5,
    float* __restrict__ out, int N, int C)
{
    __shared__ CellParam cp[CELLS];
    const int bn  = blockIdx.x;
    const int tid = threadIdx.x;

    if (tid < CELLS) {
        const int b = bn / N;
        const float* bx = boxes + (size_t)bn * 4;
        float y1 = bx[0], x1 = bx[1], y2 = bx[2], x2 = bx[3];
        float h = y2 - y1, w = x2 - x1;
        float scale = 224.0f / sqrtf(meta[4] * meta[5]);
        float lvl = log2f(sqrtf(h * w) / scale);
        float rl  = 4.0f + rintf(lvl);
        rl = fminf(fmaxf(rl, 2.0f), 5.0f);
        int li = (int)rl - 2;
        int H  = 256 >> li;
        const float* fm = (li == 0) ? f2 : (li == 1) ? f3 : (li == 2) ? f4 : f5;
        const float* base = fm + (size_t)b * H * H * C;
        int py = tid / POOL;
        int px = tid - py * POOL;
        float Hm1 = (float)(H - 1);
        float ys = y1 * Hm1 + (float)py * ((h * Hm1) / 6.0f);
        float xs = x1 * Hm1 + (float)px * ((w * Hm1) / 6.0f);
        float y0f = floorf(ys), x0f = floorf(xs);
        int y0  = min(max((int)y0f, 0), H - 1);
        int x0  = min(max((int)x0f, 0), H - 1);
        int y1i = min(y0 + 1, H - 1);
        int x1i = min(x0 + 1, H - 1);
        CellParam p;
        p.tl = (const float4*)(base + (size_t)(y0  * H + x0 ) * C);
        p.tr = (const float4*)(base + (size_t)(y0  * H + x1i) * C);
        p.bl = (const float4*)(base + (size_t)(y1i * H + x0 ) * C);
        p.br = (const float4*)(base + (size_t)(y1i * H + x1i) * C);
        p.fx = xs - x0f;  p.fy = ys - y0f;
        p.pad0 = 0.f; p.pad1 = 0.f;
        cp[tid] = p;
    }
    __syncthreads();

    const int c4pc = C >> 2;
    const int c4   = tid % c4pc;
    const int cw   = tid / c4pc;
    const int cstr = blockDim.x / c4pc;
    float4* ob = (float4*)out + (size_t)bn * CELLS * c4pc;

    for (int cell = cw; cell < CELLS; cell += cstr) {
        float fx = cp[cell].fx, fy = cp[cell].fy;
        float4 tl = __ldg(cp[cell].tl + c4);
        float4 tr = __ldg(cp[cell].tr + c4);
        float4 bl = __ldg(cp[cell].bl + c4);
        float4 br = __ldg(cp[cell].br + c4);
        ob[cell * c4pc + c4] = lerp4(tl, tr, bl, br, fx, fy);
    }
}

extern "C" void kernel_launch(void* const* d_in, const int* in_sizes, int n_in,
                              void* d_out, int out_size) {
    const float* boxes = (const float*)d_in[0];
    const float* meta  = (const float*)d_in[1];
    const float* f2    = (const float*)d_in[2];
    const float* f3    = (const float*)d_in[3];
    const float* f4    = (const float*)d_in[4];
    const float* f5    = (const float*)d_in[5];
    float* out = (float*)d_out;

    int B  = in_sizes[1] / 14;
    int N  = in_sizes[0] / (4 * B);
    int C  = in_sizes[2] / (B * 256 * 256);
    int NB = B * N;

    if (C == 256 && B == 2) {
        cvt_all_kernel<<<CVT_BLOCKS, 256>>>((const float4*)f4, (const float4*)f5);
        roialign_c256_kernel<<<NB, 256>>>(boxes, meta, f2, f3, out, N);
    } else {
        roialign_generic_kernel<<<NB, 256>>>(boxes, meta, f2, f3, f4, f5, out, N, C);
    }
}